// round 13
// baseline (speedup 1.0000x reference)
#include <cuda_runtime.h>
#include <cuda_fp16.h>
#include <math.h>
#include <stdint.h>
#include <stddef.h>

#define Bc 2
#define Lc 2048
#define Dc 2048
#define Hc 32
#define HKVc 8
#define HDc 64
#define Mtok (Bc*Lc)
#define QKVN 3072          // fused projection width: 2048 Q | 512 K | 512 V
#define QSCALE 0.18033688011112042f   // 0.125 * log2(e): S in log2 domain

typedef __half half_t;

// ---------------- scratch (__device__ globals; no allocs allowed) -----------
__device__ __align__(16) half_t g_x16[(size_t)Mtok*Dc];     // x single fp16
__device__ __align__(16) half_t g_wqkvT[(size_t)QKVN*Dc];   // single fp16
__device__ __align__(16) half_t g_woT[(size_t)Dc*Hc*HDc];   // single fp16
__device__ __align__(16) half_t g_q[(size_t)Bc*Hc*Lc*HDc];  // Q*QSCALE fp16
__device__ __align__(16) half_t g_k[(size_t)Bc*HKVc*Lc*HDc];// K single fp16
__device__ __align__(16) half_t g_v[(size_t)Bc*HKVc*Lc*HDc];// V single fp16
__device__ __align__(16) half_t g_at[(size_t)Mtok*Hc*HDc];  // attn single fp16

// ---------------- PTX helpers ----------------------------------------------
#define MMAH(CR, A, B0, B1)                                                  \
  asm volatile(                                                              \
      "mma.sync.aligned.m16n8k16.row.col.f32.f16.f16.f32 "                   \
      "{%0,%1,%2,%3},{%4,%5,%6,%7},{%8,%9},{%0,%1,%2,%3};"                   \
      : "+f"((CR)[0]), "+f"((CR)[1]), "+f"((CR)[2]), "+f"((CR)[3])           \
      : "r"((A)[0]), "r"((A)[1]), "r"((A)[2]), "r"((A)[3]), "r"(B0), "r"(B1))

#define LDSM4(R0,R1,R2,R3,ADDR)                                              \
  asm volatile("ldmatrix.sync.aligned.m8n8.x4.shared.b16 {%0,%1,%2,%3},[%4];"\
      : "=r"(R0),"=r"(R1),"=r"(R2),"=r"(R3) : "r"(ADDR))

#define LDSM4T(R0,R1,R2,R3,ADDR)                                             \
  asm volatile("ldmatrix.sync.aligned.m8n8.x4.trans.shared.b16 {%0,%1,%2,%3},[%4];"\
      : "=r"(R0),"=r"(R1),"=r"(R2),"=r"(R3) : "r"(ADDR))

__device__ __forceinline__ void cp16(uint32_t dst, const void* src){
  asm volatile("cp.async.cg.shared.global [%0], [%1], 16;" :: "r"(dst), "l"(src));
}
#define CPCOMMIT() asm volatile("cp.async.commit_group;")
#define CPWAIT0()  asm volatile("cp.async.wait_group 0;")

// ---------------- convert passes --------------------------------------------
__global__ void xcvt(const float* __restrict__ src, half_t* __restrict__ d, int n4)
{
  int i = blockIdx.x * blockDim.x + threadIdx.x;
  if (i >= n4) return;
  float4 v = ((const float4*)src)[i];
  __half2 h0 = { __float2half_rn(v.x), __float2half_rn(v.y) };
  __half2 h1 = { __float2half_rn(v.z), __float2half_rn(v.w) };
  ((__half2*)d)[2*i] = h0; ((__half2*)d)[2*i+1] = h1;
}

// One launch for all four weight transposes -> single fp16 [N][K]
__global__ void wsplit_all(const float* __restrict__ Wq,
                           const float* __restrict__ Wk,
                           const float* __restrict__ Wv,
                           const float* __restrict__ Wo,
                           half_t* __restrict__ wqkv, half_t* __restrict__ wo)
{
  const int z = blockIdx.z;
  const float* W; half_t* T; int K, N;
  if (z == 0){ W = Wq; T = wqkv;                       K = Dc;     N = Hc*HDc; }
  else if (z == 1){ W = Wk; T = wqkv + (size_t)2048*Dc; K = Dc;    N = HKVc*HDc; }
  else if (z == 2){ W = Wv; T = wqkv + (size_t)2560*Dc; K = Dc;    N = HKVc*HDc; }
  else            { W = Wo; T = wo;                     K = Hc*HDc; N = Dc; }
  if (blockIdx.x * 32 >= N) return;

  __shared__ float tile[32][33];
  int k0 = blockIdx.y*32, n0 = blockIdx.x*32;
  int tx = threadIdx.x, ty = threadIdx.y;
#pragma unroll
  for (int i = 0; i < 4; i++)
    tile[ty + 8*i][tx] = W[(size_t)(k0 + ty + 8*i) * N + n0 + tx];
  __syncthreads();
#pragma unroll
  for (int i = 0; i < 4; i++){
    int n = n0 + ty + 8*i;
    T[(size_t)n*K + k0 + tx] = __float2half_rn(tile[tx][ty + 8*i]);
  }
}

// ---------------- fused QKV GEMM + RMSNorm + RoPE + head-major fp16 ---------
#define GSTG1 32768
__global__ __launch_bounds__(256) void gemm_qkv(
    const half_t* __restrict__ A, const half_t* __restrict__ B,
    const float* __restrict__ qnw, const float* __restrict__ knw,
    half_t* __restrict__ qq, half_t* __restrict__ kk, half_t* __restrict__ vv)
{
  const int K = Dc;
  extern __shared__ char smraw[];
  const uint32_t smb = (uint32_t)__cvta_generic_to_shared(smraw);
  const int tid = threadIdx.x, lane = tid & 31, warp = tid >> 5;
  const int wm = (warp & 3) * 32, wn = (warp >> 2) * 64;
  const int g = lane >> 2, t = lane & 3;
  const int row0 = blockIdx.y * 128, col0 = blockIdx.x * 128;
  const int KI = K >> 6;

  const half_t* gsrc[2] = { A + (size_t)row0 * K, B + (size_t)col0 * K };

  auto stage = [&](int ki, int s){
#pragma unroll
    for (int q = 0; q < 2; q++)
#pragma unroll
      for (int it = 0; it < 4; it++){
        int fid = tid + it * 256;
        int row = fid >> 3, ch = fid & 7;
        cp16(smb + s*GSTG1 + q*16384 + row*128 + ((ch ^ (row & 7)) * 16),
             gsrc[q] + (size_t)row * K + ki*64 + ch*8);
      }
  };

  float c[2][8][4];
#pragma unroll
  for (int i=0;i<2;i++)
#pragma unroll
    for (int j=0;j<8;j++)
#pragma unroll
      for (int e=0;e<4;e++) c[i][j][e] = 0.f;

  stage(0, 0); CPCOMMIT();

  for (int ki = 0; ki < KI; ki++){
    int s = ki & 1;
    CPWAIT0();
    __syncthreads();
    if (ki + 1 < KI){ stage(ki + 1, s ^ 1); CPCOMMIT(); }

    const uint32_t ab = smb + s*GSTG1, bb = ab + 16384;
    const int rA  = (lane & 7) + ((lane >> 3) & 1) * 8;
    const int chA = (lane >> 4);
    const int rB  = (lane & 7) + ((lane >> 4) << 3);
    const int chB = (lane >> 3) & 1;
#pragma unroll
    for (int kc = 0; kc < 4; kc++){
      uint32_t ah[2][4];
#pragma unroll
      for (int mt = 0; mt < 2; mt++){
        int r = wm + mt*16 + rA;
        int ch = kc*2 + chA;
        uint32_t ad = ab + r*128 + ((ch ^ (r & 7)) * 16);
        LDSM4(ah[mt][0], ah[mt][1], ah[mt][2], ah[mt][3], ad);
      }
#pragma unroll
      for (int ntp = 0; ntp < 4; ntp++){
        int r = wn + ntp*16 + rB;
        int ch = kc*2 + chB;
        uint32_t ad = bb + r*128 + ((ch ^ (r & 7)) * 16);
        uint32_t b0,b1,b2,b3;
        LDSM4(b0,b1,b2,b3, ad);
#pragma unroll
        for (int mt = 0; mt < 2; mt++){
          MMAH(c[mt][2*ntp],   ah[mt], b0, b1);
          MMAH(c[mt][2*ntp+1], ah[mt], b2, b3);
        }
      }
    }
    __syncthreads();
  }

  // ---- fused epilogue: RMSNorm + RoPE + head-major fp16 ----
  const int gcol = col0 + wn;
  int mode, nh, head;
  const float* w = qnw;
  if (gcol < 2048)      { mode = 0; nh = Hc;   head = gcol >> 6; w = qnw; }
  else if (gcol < 2560) { mode = 1; nh = HKVc; head = (gcol - 2048) >> 6; w = knw; }
  else                  { mode = 2; nh = HKVc; head = (gcol - 2560) >> 6; }

  float invf[8];
  if (mode < 2){
#pragma unroll
    for (int nt = 0; nt < 4; nt++){
      int d0 = nt*8 + 2*t;
      invf[2*nt]   = powf(1000000.0f, -((float)(2*d0))     * (1.0f/64.0f));
      invf[2*nt+1] = powf(1000000.0f, -((float)(2*(d0+1))) * (1.0f/64.0f));
    }
  }
  const float oscale = (mode == 0) ? QSCALE : 1.0f;

#pragma unroll
  for (int mt = 0; mt < 2; mt++){
    int r0 = row0 + wm + mt*16 + g;
    float rn0 = 0.f, rn1 = 0.f;
    if (mode < 2){
      float ss0 = 0.f, ss1 = 0.f;
#pragma unroll
      for (int nt = 0; nt < 8; nt++){
        ss0 += c[mt][nt][0]*c[mt][nt][0] + c[mt][nt][1]*c[mt][nt][1];
        ss1 += c[mt][nt][2]*c[mt][nt][2] + c[mt][nt][3]*c[mt][nt][3];
      }
      ss0 += __shfl_xor_sync(0xffffffffu, ss0, 1);
      ss0 += __shfl_xor_sync(0xffffffffu, ss0, 2);
      ss1 += __shfl_xor_sync(0xffffffffu, ss1, 1);
      ss1 += __shfl_xor_sync(0xffffffffu, ss1, 2);
      rn0 = rsqrtf(ss0 * (1.0f/64.0f) + 1e-5f);
      rn1 = rsqrtf(ss1 * (1.0f/64.0f) + 1e-5f);
    }

#pragma unroll
    for (int half2row = 0; half2row < 2; half2row++){
      int r = r0 + half2row*8;
      int e = half2row*2;
      float rn = half2row ? rn1 : rn0;
      int pos = r & (Lc-1);
      int b = r >> 11;
      size_t base = ((size_t)(b*nh + head)*Lc + pos) * HDc;

      if (mode == 2){
#pragma unroll
        for (int nt = 0; nt < 8; nt++){
          int d0 = nt*8 + 2*t;
          __half2 v2 = { __float2half_rn(c[mt][nt][e]), __float2half_rn(c[mt][nt][e+1]) };
          *(__half2*)(vv + base + d0) = v2;
        }
      } else {
        float fpos = (float)pos;
        half_t* dst = (mode == 0) ? qq : kk;
#pragma unroll
        for (int nt = 0; nt < 4; nt++){
          int d0 = nt*8 + 2*t;
          float x1a = c[mt][nt][e]   * rn * w[d0];
          float x1b = c[mt][nt][e+1] * rn * w[d0+1];
          float x2a = c[mt][nt+4][e]   * rn * w[d0+32];
          float x2b = c[mt][nt+4][e+1] * rn * w[d0+33];
          float anga = fpos * invf[2*nt],  angb = fpos * invf[2*nt+1];
          float ca = cosf(anga), sa = sinf(anga);
          float cb = cosf(angb), sb = sinf(angb);
          float y1a = (x1a*ca - x2a*sa) * oscale,  y1b = (x1b*cb - x2b*sb) * oscale;
          float y2a = (x2a*ca + x1a*sa) * oscale,  y2b = (x2b*cb + x1b*sb) * oscale;
          __half2 v1 = { __float2half_rn(y1a), __float2half_rn(y1b) };
          __half2 v2 = { __float2half_rn(y2a), __float2half_rn(y2b) };
          *(__half2*)(dst + base + d0)      = v1;
          *(__half2*)(dst + base + d0 + 32) = v2;
        }
      }
    }
  }
}

// ---------------- single fp16 tensor-core GEMM (Wo) -------------------------
__global__ __launch_bounds__(256) void gemm_fp16(
    const half_t* __restrict__ A, const half_t* __restrict__ B,
    float* __restrict__ C, int M, int N, int K)
{
  extern __shared__ char smraw[];
  const uint32_t smb = (uint32_t)__cvta_generic_to_shared(smraw);
  const int tid = threadIdx.x, lane = tid & 31, warp = tid >> 5;
  const int wm = (warp & 3) * 32, wn = (warp >> 2) * 64;
  const int g = lane >> 2, t = lane & 3;
  const int row0 = blockIdx.y * 128, col0 = blockIdx.x * 128;
  const int KI = K >> 6;

  const half_t* gsrc[2] = { A + (size_t)row0 * K, B + (size_t)col0 * K };

  auto stage = [&](int ki, int s){
#pragma unroll
    for (int q = 0; q < 2; q++)
#pragma unroll
      for (int it = 0; it < 4; it++){
        int fid = tid + it * 256;
        int row = fid >> 3, ch = fid & 7;
        cp16(smb + s*GSTG1 + q*16384 + row*128 + ((ch ^ (row & 7)) * 16),
             gsrc[q] + (size_t)row * K + ki*64 + ch*8);
      }
  };

  float c[2][8][4];
#pragma unroll
  for (int i=0;i<2;i++)
#pragma unroll
    for (int j=0;j<8;j++)
#pragma unroll
      for (int e=0;e<4;e++) c[i][j][e] = 0.f;

  stage(0, 0); CPCOMMIT();

  for (int ki = 0; ki < KI; ki++){
    int s = ki & 1;
    CPWAIT0();
    __syncthreads();
    if (ki + 1 < KI){ stage(ki + 1, s ^ 1); CPCOMMIT(); }

    const uint32_t ab = smb + s*GSTG1, bb = ab + 16384;
    const int rA  = (lane & 7) + ((lane >> 3) & 1) * 8;
    const int chA = (lane >> 4);
    const int rB  = (lane & 7) + ((lane >> 4) << 3);
    const int chB = (lane >> 3) & 1;
#pragma unroll
    for (int kc = 0; kc < 4; kc++){
      uint32_t ah[2][4];
#pragma unroll
      for (int mt = 0; mt < 2; mt++){
        int r = wm + mt*16 + rA;
        int ch = kc*2 + chA;
        uint32_t ad = ab + r*128 + ((ch ^ (r & 7)) * 16);
        LDSM4(ah[mt][0], ah[mt][1], ah[mt][2], ah[mt][3], ad);
      }
#pragma unroll
      for (int ntp = 0; ntp < 4; ntp++){
        int r = wn + ntp*16 + rB;
        int ch = kc*2 + chB;
        uint32_t ad = bb + r*128 + ((ch ^ (r & 7)) * 16);
        uint32_t b0,b1,b2,b3;
        LDSM4(b0,b1,b2,b3, ad);
#pragma unroll
        for (int mt = 0; mt < 2; mt++){
          MMAH(c[mt][2*ntp],   ah[mt], b0, b1);
          MMAH(c[mt][2*ntp+1], ah[mt], b2, b3);
        }
      }
    }
    __syncthreads();
  }

#pragma unroll
  for (int mt = 0; mt < 2; mt++)
#pragma unroll
    for (int nt = 0; nt < 8; nt++){
      int r = row0 + wm + mt*16 + g;
      int cc = col0 + wn + nt*8 + 2*t;
      float2 v0 = { c[mt][nt][0], c[mt][nt][1] };
      float2 v1 = { c[mt][nt][2], c[mt][nt][3] };
      *(float2*)(C + (size_t)r * N + cc) = v0;
      *(float2*)(C + (size_t)(r + 8) * N + cc) = v1;
    }
}

// ---------------- tensor-core flash attention -------------------------------
// 128-row Q tile, 256 threads (8 warps x 16 rows), 64-key chunks, shared KV.
// smem: Q 16K | 2 stages x (K 8K | V 8K) = 48K. 2 CTAs/SM (reg-bound).
#define FSM_KV  16384
#define KV_STG  16384
#define FLASH_SMEM (16384 + 2*KV_STG)

__global__ __launch_bounds__(256, 2) void flash_tc(
    const half_t* __restrict__ Qp, const half_t* __restrict__ Kp,
    const half_t* __restrict__ Vp, half_t* __restrict__ O)
{
  extern __shared__ char smraw[];
  const uint32_t smb = (uint32_t)__cvta_generic_to_shared(smraw);
  const int tid = threadIdx.x, lane = tid & 31, warp = tid >> 5;
  const int qt = gridDim.x - 1 - blockIdx.x;   // big tiles first
  const int h = blockIdx.y, b = blockIdx.z, hkv = h >> 2;
  const int g = lane >> 2, t = lane & 3;

  const half_t* qp = Qp + ((size_t)(b*Hc + h)*Lc + qt*128) * HDc;
  const size_t kvoff = (size_t)(b*HKVc + hkv) * Lc * HDc;
  const half_t* kvsrc[2] = { Kp + kvoff, Vp + kvoff };

  // stage Q (once): 128 rows x 64 cols fp16 (pre-scaled by 0.125*log2e)
#pragma unroll
  for (int it = 0; it < 4; it++){
    int fid = tid + it * 256;
    int row = fid >> 3, ch = fid & 7;
    uint4 v4 = *(const uint4*)(qp + row*64 + ch*8);
    *(uint4*)(smraw + row*128 + ((ch ^ (row & 7)) * 16)) = v4;
  }

  auto stageKV = [&](int j, int s){
#pragma unroll
    for (int q = 0; q < 2; q++)
#pragma unroll
      for (int it = 0; it < 2; it++){
        int fid = tid + it * 256;          // 0..511: 64 rows x 8 chunks
        int row = fid >> 3, ch = fid & 7;
        cp16(smb + FSM_KV + s*KV_STG + q*8192 + row*128 + ((ch ^ (row & 7))*16),
             kvsrc[q] + (size_t)(j*64 + row)*64 + ch*8);
      }
  };

  stageKV(0, 0); CPCOMMIT();
  __syncthreads();

  // Q fragments (persistent; this warp's 16 rows)
  uint32_t qf[4][4];
  {
    int r = warp*16 + (lane & 7) + ((lane >> 3) & 1) * 8;
#pragma unroll
    for (int kc = 0; kc < 4; kc++){
      int ch = kc*2 + (lane >> 4);
      uint32_t ad = smb + r*128 + ((ch ^ (r & 7)) * 16);
      LDSM4(qf[kc][0], qf[kc][1], qf[kc][2], qf[kc][3], ad);
    }
  }

  float o[8][4];
#pragma unroll
  for (int nt=0;nt<8;nt++)
#pragma unroll
    for (int e=0;e<4;e++) o[nt][e] = 0.f;
  float m0r = -1e30f, m1r = -1e30f, l0 = 0.f, l1 = 0.f;

  const int r0g = qt*128 + warp*16 + g;
  const int r1g = r0g + 8;
  const int rBv = (lane & 7) + ((lane >> 4) << 3);
  const int chBv = (lane >> 3) & 1;
  const int rVv = (lane & 7) + (((lane >> 3) & 1) << 3);
  const int chVv = lane >> 4;
  const int jmax = 2*qt + 1;               // 64-key tiles: 0..2qt+1

  for (int j = 0; j <= jmax; j++){
    int s = j & 1;
    CPWAIT0();
    __syncthreads();
    if (j < jmax){ stageKV(j + 1, s ^ 1); CPCOMMIT(); }

    const uint32_t kb = smb + FSM_KV + s*KV_STG;

    float sf[8][4];
#pragma unroll
    for (int nt=0;nt<8;nt++)
#pragma unroll
      for (int e=0;e<4;e++) sf[nt][e] = 0.f;

    // S = Q K^T (log2 domain)
#pragma unroll
    for (int kc = 0; kc < 4; kc++){
#pragma unroll
      for (int ntp = 0; ntp < 4; ntp++){
        int r = ntp*16 + rBv;
        int ch = kc*2 + chBv;
        uint32_t ad = kb + r*128 + ((ch ^ (r & 7)) * 16);
        uint32_t b0,b1,b2,b3;
        LDSM4(b0,b1,b2,b3, ad);
        MMAH(sf[2*ntp],   qf[kc], b0, b1);
        MMAH(sf[2*ntp+1], qf[kc], b2, b3);
      }
    }

    // causal mask + row max
    if (j*64 + 63 > r0g){
#pragma unroll
      for (int nt = 0; nt < 8; nt++){
        int c0 = j*64 + nt*8 + 2*t;
        if (c0     > r0g) sf[nt][0] = -1e30f;
        if (c0 + 1 > r0g) sf[nt][1] = -1e30f;
        if (c0     > r1g) sf[nt][2] = -1e30f;
        if (c0 + 1 > r1g) sf[nt][3] = -1e30f;
      }
    }
    float tm0 = -1e30f, tm1 = -1e30f;
#pragma unroll
    for (int nt = 0; nt < 8; nt++){
      tm0 = fmaxf(tm0, fmaxf(sf[nt][0], sf[nt][1]));
      tm1 = fmaxf(tm1, fmaxf(sf[nt][2], sf[nt][3]));
    }
    tm0 = fmaxf(tm0, __shfl_xor_sync(0xffffffffu, tm0, 1));
    tm0 = fmaxf(tm0, __shfl_xor_sync(0xffffffffu, tm0, 2));
    tm1 = fmaxf(tm1, __shfl_xor_sync(0xffffffffu, tm1, 1));
    tm1 = fmaxf(tm1, __shfl_xor_sync(0xffffffffu, tm1, 2));

    float mn0 = fmaxf(m0r, tm0), mn1 = fmaxf(m1r, tm1);
    float corr0 = exp2f(m0r - mn0), corr1 = exp2f(m1r - mn1);

    // P = 2^(s - mn) in fp16x2 — output IS the packed A-fragment
    uint32_t pf[16];
    float s0 = 0.f, s1 = 0.f;
#pragma unroll
    for (int nt = 0; nt < 8; nt++){
      __half2 e0 = h2exp2(__floats2half2_rn(sf[nt][0]-mn0, sf[nt][1]-mn0));
      __half2 e1 = h2exp2(__floats2half2_rn(sf[nt][2]-mn1, sf[nt][3]-mn1));
      pf[2*nt]   = *(uint32_t*)&e0;
      pf[2*nt+1] = *(uint32_t*)&e1;
      float2 f0 = __half22float2(e0), f1 = __half22float2(e1);
      s0 += f0.x + f0.y;  s1 += f1.x + f1.y;
    }
    s0 += __shfl_xor_sync(0xffffffffu, s0, 1);
    s0 += __shfl_xor_sync(0xffffffffu, s0, 2);
    s1 += __shfl_xor_sync(0xffffffffu, s1, 1);
    s1 += __shfl_xor_sync(0xffffffffu, s1, 2);
    l0 = l0*corr0 + s0;  l1 = l1*corr1 + s1;
    m0r = mn0;  m1r = mn1;
#pragma unroll
    for (int nt = 0; nt < 8; nt++){
      o[nt][0] *= corr0; o[nt][1] *= corr0;
      o[nt][2] *= corr1; o[nt][3] *= corr1;
    }

    // O += P V
    const uint32_t vb = kb + 8192;
#pragma unroll
    for (int kc = 0; kc < 4; kc++){
      uint32_t ph[4] = { pf[4*kc], pf[4*kc+1], pf[4*kc+2], pf[4*kc+3] };
#pragma unroll
      for (int ntp = 0; ntp < 4; ntp++){
        int r = kc*16 + rVv;
        int ch = ntp*2 + chVv;
        uint32_t ad = vb + r*128 + ((ch ^ (r & 7)) * 16);
        uint32_t w0,w1,w2,w3;
        LDSM4T(w0,w1,w2,w3, ad);
        MMAH(o[2*ntp],   ph, w0, w1);
        MMAH(o[2*ntp+1], ph, w2, w3);
      }
    }
  }

  // epilogue: normalize, write single fp16 attn [b][l][h][d]
  float inv0 = 1.f / l0, inv1 = 1.f / l1;
  size_t ob0 = ((size_t)(b*Lc + qt*128 + warp*16 + g) * Hc + h) * HDc;
  size_t ob1 = ob0 + (size_t)8 * Hc * HDc;
#pragma unroll
  for (int nt = 0; nt < 8; nt++){
    int d = nt*8 + 2*t;
    __half2 a = { __float2half_rn(o[nt][0]*inv0), __float2half_rn(o[nt][1]*inv0) };
    __half2 c = { __float2half_rn(o[nt][2]*inv1), __float2half_rn(o[nt][3]*inv1) };
    *(__half2*)(O + ob0 + d) = a;
    *(__half2*)(O + ob1 + d) = c;
  }
}

// ---------------------------------------------------------------------------
extern "C" void kernel_launch(void* const* d_in, const int* in_sizes, int n_in,
                              void* d_out, int out_size)
{
  const float* x   = (const float*)d_in[0];
  const float* Wq  = (const float*)d_in[1];
  const float* Wk  = (const float*)d_in[2];
  const float* Wv  = (const float*)d_in[3];
  const float* Wo  = (const float*)d_in[4];
  const float* qnw = (const float*)d_in[5];
  const float* knw = (const float*)d_in[6];
  float* out = (float*)d_out;

  half_t *x16,*wqkv,*wo,*at,*qq,*kk,*vv;
  cudaGetSymbolAddress((void**)&x16, g_x16);
  cudaGetSymbolAddress((void**)&wqkv, g_wqkvT);
  cudaGetSymbolAddress((void**)&wo, g_woT);
  cudaGetSymbolAddress((void**)&qq, g_q);
  cudaGetSymbolAddress((void**)&kk, g_k);  cudaGetSymbolAddress((void**)&vv, g_v);
  cudaGetSymbolAddress((void**)&at, g_at);

  const int M = Mtok;

  // (1) activation convert
  xcvt<<<(M*Dc/4 + 255)/256, 256>>>(x, x16, M*Dc/4);
  // (2) all weight transposes in one launch
  wsplit_all<<<dim3(64, 64, 4), dim3(32,8)>>>(Wq, Wk, Wv, Wo, wqkv, wo);

  // (3) fused QKV projection + RMSNorm + RoPE -> head-major fp16
  cudaFuncSetAttribute(gemm_qkv, cudaFuncAttributeMaxDynamicSharedMemorySize, 2*GSTG1);
  gemm_qkv<<<dim3(QKVN/128, M/128), 256, 2*GSTG1>>>(x16, wqkv, qnw, knw, qq, kk, vv);

  // (4) flash attention (128-row q tiles, 8 warps)
  cudaFuncSetAttribute(flash_tc, cudaFuncAttributeMaxDynamicSharedMemorySize, FLASH_SMEM);
  flash_tc<<<dim3(Lc/128, Hc, Bc), 256, FLASH_SMEM>>>(qq, kk, vv, at);

  // (5) output projection
  cudaFuncSetAttribute(gemm_fp16, cudaFuncAttributeMaxDynamicSharedMemorySize, 2*GSTG1);
  gemm_fp16<<<dim3(Dc/128, M/128), 256, 2*GSTG1>>>(at, wo, out, M, Dc, Dc);
}

// round 14
// speedup vs baseline: 1.0719x; 1.0719x over previous
#include <cuda_runtime.h>
#include <cuda_fp16.h>
#include <math.h>
#include <stdint.h>
#include <stddef.h>

#define Bc 2
#define Lc 2048
#define Dc 2048
#define Hc 32
#define HKVc 8
#define HDc 64
#define Mtok (Bc*Lc)
#define QKVN 3072          // fused projection width: 2048 Q | 512 K | 512 V
#define QSCALE 0.18033688011112042f   // 0.125 * log2(e): S in log2 domain

typedef __half half_t;

// ---------------- scratch (__device__ globals; no allocs allowed) -----------
__device__ __align__(16) half_t g_x16[(size_t)Mtok*Dc];     // x single fp16
__device__ __align__(16) half_t g_wqkvT[(size_t)QKVN*Dc];   // single fp16
__device__ __align__(16) half_t g_woT[(size_t)Dc*Hc*HDc];   // single fp16
__device__ __align__(16) half_t g_q[(size_t)Bc*Hc*Lc*HDc];  // Q*QSCALE fp16
__device__ __align__(16) half_t g_k[(size_t)Bc*HKVc*Lc*HDc];// K single fp16
__device__ __align__(16) half_t g_v[(size_t)Bc*HKVc*Lc*HDc];// V single fp16
__device__ __align__(16) half_t g_at[(size_t)Mtok*Hc*HDc];  // attn single fp16

// ---------------- PTX helpers ----------------------------------------------
#define MMAH(CR, A, B0, B1)                                                  \
  asm volatile(                                                              \
      "mma.sync.aligned.m16n8k16.row.col.f32.f16.f16.f32 "                   \
      "{%0,%1,%2,%3},{%4,%5,%6,%7},{%8,%9},{%0,%1,%2,%3};"                   \
      : "+f"((CR)[0]), "+f"((CR)[1]), "+f"((CR)[2]), "+f"((CR)[3])           \
      : "r"((A)[0]), "r"((A)[1]), "r"((A)[2]), "r"((A)[3]), "r"(B0), "r"(B1))

#define LDSM4(R0,R1,R2,R3,ADDR)                                              \
  asm volatile("ldmatrix.sync.aligned.m8n8.x4.shared.b16 {%0,%1,%2,%3},[%4];"\
      : "=r"(R0),"=r"(R1),"=r"(R2),"=r"(R3) : "r"(ADDR))

#define LDSM4T(R0,R1,R2,R3,ADDR)                                             \
  asm volatile("ldmatrix.sync.aligned.m8n8.x4.trans.shared.b16 {%0,%1,%2,%3},[%4];"\
      : "=r"(R0),"=r"(R1),"=r"(R2),"=r"(R3) : "r"(ADDR))

__device__ __forceinline__ void cp16(uint32_t dst, const void* src){
  asm volatile("cp.async.cg.shared.global [%0], [%1], 16;" :: "r"(dst), "l"(src));
}
#define CPCOMMIT() asm volatile("cp.async.commit_group;")
#define CPWAIT0()  asm volatile("cp.async.wait_group 0;")

// ---------------- convert passes --------------------------------------------
__global__ void xcvt(const float* __restrict__ src, half_t* __restrict__ d, int n4)
{
  int i = blockIdx.x * blockDim.x + threadIdx.x;
  if (i >= n4) return;
  float4 v = ((const float4*)src)[i];
  __half2 h0 = { __float2half_rn(v.x), __float2half_rn(v.y) };
  __half2 h1 = { __float2half_rn(v.z), __float2half_rn(v.w) };
  ((__half2*)d)[2*i] = h0; ((__half2*)d)[2*i+1] = h1;
}

// One launch for all four weight transposes -> single fp16 [N][K]
__global__ void wsplit_all(const float* __restrict__ Wq,
                           const float* __restrict__ Wk,
                           const float* __restrict__ Wv,
                           const float* __restrict__ Wo,
                           half_t* __restrict__ wqkv, half_t* __restrict__ wo)
{
  const int z = blockIdx.z;
  const float* W; half_t* T; int K, N;
  if (z == 0){ W = Wq; T = wqkv;                       K = Dc;     N = Hc*HDc; }
  else if (z == 1){ W = Wk; T = wqkv + (size_t)2048*Dc; K = Dc;    N = HKVc*HDc; }
  else if (z == 2){ W = Wv; T = wqkv + (size_t)2560*Dc; K = Dc;    N = HKVc*HDc; }
  else            { W = Wo; T = wo;                     K = Hc*HDc; N = Dc; }
  if (blockIdx.x * 32 >= N) return;

  __shared__ float tile[32][33];
  int k0 = blockIdx.y*32, n0 = blockIdx.x*32;
  int tx = threadIdx.x, ty = threadIdx.y;
#pragma unroll
  for (int i = 0; i < 4; i++)
    tile[ty + 8*i][tx] = W[(size_t)(k0 + ty + 8*i) * N + n0 + tx];
  __syncthreads();
#pragma unroll
  for (int i = 0; i < 4; i++){
    int n = n0 + ty + 8*i;
    T[(size_t)n*K + k0 + tx] = __float2half_rn(tile[tx][ty + 8*i]);
  }
}

// ---------------- fused QKV GEMM + RMSNorm + RoPE + head-major fp16 ---------
#define GSTG1 32768
__global__ __launch_bounds__(256) void gemm_qkv(
    const half_t* __restrict__ A, const half_t* __restrict__ B,
    const float* __restrict__ qnw, const float* __restrict__ knw,
    half_t* __restrict__ qq, half_t* __restrict__ kk, half_t* __restrict__ vv)
{
  const int K = Dc;
  extern __shared__ char smraw[];
  const uint32_t smb = (uint32_t)__cvta_generic_to_shared(smraw);
  const int tid = threadIdx.x, lane = tid & 31, warp = tid >> 5;
  const int wm = (warp & 3) * 32, wn = (warp >> 2) * 64;
  const int g = lane >> 2, t = lane & 3;
  const int row0 = blockIdx.y * 128, col0 = blockIdx.x * 128;
  const int KI = K >> 6;

  const half_t* gsrc[2] = { A + (size_t)row0 * K, B + (size_t)col0 * K };

  auto stage = [&](int ki, int s){
#pragma unroll
    for (int q = 0; q < 2; q++)
#pragma unroll
      for (int it = 0; it < 4; it++){
        int fid = tid + it * 256;
        int row = fid >> 3, ch = fid & 7;
        cp16(smb + s*GSTG1 + q*16384 + row*128 + ((ch ^ (row & 7)) * 16),
             gsrc[q] + (size_t)row * K + ki*64 + ch*8);
      }
  };

  float c[2][8][4];
#pragma unroll
  for (int i=0;i<2;i++)
#pragma unroll
    for (int j=0;j<8;j++)
#pragma unroll
      for (int e=0;e<4;e++) c[i][j][e] = 0.f;

  stage(0, 0); CPCOMMIT();

  for (int ki = 0; ki < KI; ki++){
    int s = ki & 1;
    CPWAIT0();
    __syncthreads();
    if (ki + 1 < KI){ stage(ki + 1, s ^ 1); CPCOMMIT(); }

    const uint32_t ab = smb + s*GSTG1, bb = ab + 16384;
    const int rA  = (lane & 7) + ((lane >> 3) & 1) * 8;
    const int chA = (lane >> 4);
    const int rB  = (lane & 7) + ((lane >> 4) << 3);
    const int chB = (lane >> 3) & 1;
#pragma unroll
    for (int kc = 0; kc < 4; kc++){
      uint32_t ah[2][4];
#pragma unroll
      for (int mt = 0; mt < 2; mt++){
        int r = wm + mt*16 + rA;
        int ch = kc*2 + chA;
        uint32_t ad = ab + r*128 + ((ch ^ (r & 7)) * 16);
        LDSM4(ah[mt][0], ah[mt][1], ah[mt][2], ah[mt][3], ad);
      }
#pragma unroll
      for (int ntp = 0; ntp < 4; ntp++){
        int r = wn + ntp*16 + rB;
        int ch = kc*2 + chB;
        uint32_t ad = bb + r*128 + ((ch ^ (r & 7)) * 16);
        uint32_t b0,b1,b2,b3;
        LDSM4(b0,b1,b2,b3, ad);
#pragma unroll
        for (int mt = 0; mt < 2; mt++){
          MMAH(c[mt][2*ntp],   ah[mt], b0, b1);
          MMAH(c[mt][2*ntp+1], ah[mt], b2, b3);
        }
      }
    }
    __syncthreads();
  }

  // ---- fused epilogue: RMSNorm + RoPE + head-major fp16 ----
  const int gcol = col0 + wn;
  int mode, nh, head;
  const float* w = qnw;
  if (gcol < 2048)      { mode = 0; nh = Hc;   head = gcol >> 6; w = qnw; }
  else if (gcol < 2560) { mode = 1; nh = HKVc; head = (gcol - 2048) >> 6; w = knw; }
  else                  { mode = 2; nh = HKVc; head = (gcol - 2560) >> 6; }

  float invf[8];
  if (mode < 2){
#pragma unroll
    for (int nt = 0; nt < 4; nt++){
      int d0 = nt*8 + 2*t;
      invf[2*nt]   = powf(1000000.0f, -((float)(2*d0))     * (1.0f/64.0f));
      invf[2*nt+1] = powf(1000000.0f, -((float)(2*(d0+1))) * (1.0f/64.0f));
    }
  }
  const float oscale = (mode == 0) ? QSCALE : 1.0f;

#pragma unroll
  for (int mt = 0; mt < 2; mt++){
    int r0 = row0 + wm + mt*16 + g;
    float rn0 = 0.f, rn1 = 0.f;
    if (mode < 2){
      float ss0 = 0.f, ss1 = 0.f;
#pragma unroll
      for (int nt = 0; nt < 8; nt++){
        ss0 += c[mt][nt][0]*c[mt][nt][0] + c[mt][nt][1]*c[mt][nt][1];
        ss1 += c[mt][nt][2]*c[mt][nt][2] + c[mt][nt][3]*c[mt][nt][3];
      }
      ss0 += __shfl_xor_sync(0xffffffffu, ss0, 1);
      ss0 += __shfl_xor_sync(0xffffffffu, ss0, 2);
      ss1 += __shfl_xor_sync(0xffffffffu, ss1, 1);
      ss1 += __shfl_xor_sync(0xffffffffu, ss1, 2);
      rn0 = rsqrtf(ss0 * (1.0f/64.0f) + 1e-5f);
      rn1 = rsqrtf(ss1 * (1.0f/64.0f) + 1e-5f);
    }

#pragma unroll
    for (int half2row = 0; half2row < 2; half2row++){
      int r = r0 + half2row*8;
      int e = half2row*2;
      float rn = half2row ? rn1 : rn0;
      int pos = r & (Lc-1);
      int b = r >> 11;
      size_t base = ((size_t)(b*nh + head)*Lc + pos) * HDc;

      if (mode == 2){
#pragma unroll
        for (int nt = 0; nt < 8; nt++){
          int d0 = nt*8 + 2*t;
          __half2 v2 = { __float2half_rn(c[mt][nt][e]), __float2half_rn(c[mt][nt][e+1]) };
          *(__half2*)(vv + base + d0) = v2;
        }
      } else {
        float fpos = (float)pos;
        half_t* dst = (mode == 0) ? qq : kk;
#pragma unroll
        for (int nt = 0; nt < 4; nt++){
          int d0 = nt*8 + 2*t;
          float x1a = c[mt][nt][e]   * rn * w[d0];
          float x1b = c[mt][nt][e+1] * rn * w[d0+1];
          float x2a = c[mt][nt+4][e]   * rn * w[d0+32];
          float x2b = c[mt][nt+4][e+1] * rn * w[d0+33];
          float anga = fpos * invf[2*nt],  angb = fpos * invf[2*nt+1];
          float ca = cosf(anga), sa = sinf(anga);
          float cb = cosf(angb), sb = sinf(angb);
          float y1a = (x1a*ca - x2a*sa) * oscale,  y1b = (x1b*cb - x2b*sb) * oscale;
          float y2a = (x2a*ca + x1a*sa) * oscale,  y2b = (x2b*cb + x1b*sb) * oscale;
          __half2 v1 = { __float2half_rn(y1a), __float2half_rn(y1b) };
          __half2 v2 = { __float2half_rn(y2a), __float2half_rn(y2b) };
          *(__half2*)(dst + base + d0)      = v1;
          *(__half2*)(dst + base + d0 + 32) = v2;
        }
      }
    }
  }
}

// ---------------- single fp16 tensor-core GEMM (Wo) -------------------------
__global__ __launch_bounds__(256) void gemm_fp16(
    const half_t* __restrict__ A, const half_t* __restrict__ B,
    float* __restrict__ C, int M, int N, int K)
{
  extern __shared__ char smraw[];
  const uint32_t smb = (uint32_t)__cvta_generic_to_shared(smraw);
  const int tid = threadIdx.x, lane = tid & 31, warp = tid >> 5;
  const int wm = (warp & 3) * 32, wn = (warp >> 2) * 64;
  const int g = lane >> 2, t = lane & 3;
  const int row0 = blockIdx.y * 128, col0 = blockIdx.x * 128;
  const int KI = K >> 6;

  const half_t* gsrc[2] = { A + (size_t)row0 * K, B + (size_t)col0 * K };

  auto stage = [&](int ki, int s){
#pragma unroll
    for (int q = 0; q < 2; q++)
#pragma unroll
      for (int it = 0; it < 4; it++){
        int fid = tid + it * 256;
        int row = fid >> 3, ch = fid & 7;
        cp16(smb + s*GSTG1 + q*16384 + row*128 + ((ch ^ (row & 7)) * 16),
             gsrc[q] + (size_t)row * K + ki*64 + ch*8);
      }
  };

  float c[2][8][4];
#pragma unroll
  for (int i=0;i<2;i++)
#pragma unroll
    for (int j=0;j<8;j++)
#pragma unroll
      for (int e=0;e<4;e++) c[i][j][e] = 0.f;

  stage(0, 0); CPCOMMIT();

  for (int ki = 0; ki < KI; ki++){
    int s = ki & 1;
    CPWAIT0();
    __syncthreads();
    if (ki + 1 < KI){ stage(ki + 1, s ^ 1); CPCOMMIT(); }

    const uint32_t ab = smb + s*GSTG1, bb = ab + 16384;
    const int rA  = (lane & 7) + ((lane >> 3) & 1) * 8;
    const int chA = (lane >> 4);
    const int rB  = (lane & 7) + ((lane >> 4) << 3);
    const int chB = (lane >> 3) & 1;
#pragma unroll
    for (int kc = 0; kc < 4; kc++){
      uint32_t ah[2][4];
#pragma unroll
      for (int mt = 0; mt < 2; mt++){
        int r = wm + mt*16 + rA;
        int ch = kc*2 + chA;
        uint32_t ad = ab + r*128 + ((ch ^ (r & 7)) * 16);
        LDSM4(ah[mt][0], ah[mt][1], ah[mt][2], ah[mt][3], ad);
      }
#pragma unroll
      for (int ntp = 0; ntp < 4; ntp++){
        int r = wn + ntp*16 + rB;
        int ch = kc*2 + chB;
        uint32_t ad = bb + r*128 + ((ch ^ (r & 7)) * 16);
        uint32_t b0,b1,b2,b3;
        LDSM4(b0,b1,b2,b3, ad);
#pragma unroll
        for (int mt = 0; mt < 2; mt++){
          MMAH(c[mt][2*ntp],   ah[mt], b0, b1);
          MMAH(c[mt][2*ntp+1], ah[mt], b2, b3);
        }
      }
    }
    __syncthreads();
  }

#pragma unroll
  for (int mt = 0; mt < 2; mt++)
#pragma unroll
    for (int nt = 0; nt < 8; nt++){
      int r = row0 + wm + mt*16 + g;
      int cc = col0 + wn + nt*8 + 2*t;
      float2 v0 = { c[mt][nt][0], c[mt][nt][1] };
      float2 v1 = { c[mt][nt][2], c[mt][nt][3] };
      *(float2*)(C + (size_t)r * N + cc) = v0;
      *(float2*)(C + (size_t)(r + 8) * N + cc) = v1;
    }
}

// ---------------- flash attention: MAX-FREE softmax -------------------------
// P = 2^s directly (s <= 11.54 provably, P <= 2980 < fp16 max). No row max,
// no correction, no per-tile shfl. l reduced once after the loop.
// 64-row Q tile, 128 threads, smem 40K, 4 CTAs/SM.
#define FSM_KV  8192
#define KV_STG  16384
#define FLASH_SMEM (8192 + 2*KV_STG)

__global__ __launch_bounds__(128, 4) void flash_tc(
    const half_t* __restrict__ Qp, const half_t* __restrict__ Kp,
    const half_t* __restrict__ Vp, half_t* __restrict__ O)
{
  extern __shared__ char smraw[];
  const uint32_t smb = (uint32_t)__cvta_generic_to_shared(smraw);
  const int tid = threadIdx.x, lane = tid & 31, warp = tid >> 5;
  const int qt = gridDim.x - 1 - blockIdx.x;   // big tiles first
  const int h = blockIdx.y, b = blockIdx.z, hkv = h >> 2;
  const int g = lane >> 2, t = lane & 3;

  const half_t* qp = Qp + ((size_t)(b*Hc + h)*Lc + qt*64) * HDc;
  const size_t kvoff = (size_t)(b*HKVc + hkv) * Lc * HDc;
  const half_t* kvsrc[2] = { Kp + kvoff, Vp + kvoff };

  // stage Q (once)
#pragma unroll
  for (int it = 0; it < 4; it++){
    int fid = tid + it * 128;
    int row = fid >> 3, ch = fid & 7;
    uint4 v4 = *(const uint4*)(qp + row*64 + ch*8);
    *(uint4*)(smraw + row*128 + ((ch ^ (row & 7)) * 16)) = v4;
  }

  auto stageKV = [&](int j, int s){
#pragma unroll
    for (int q = 0; q < 2; q++)
#pragma unroll
      for (int it = 0; it < 4; it++){
        int fid = tid + it * 128;
        int row = fid >> 3, ch = fid & 7;
        cp16(smb + FSM_KV + s*KV_STG + q*8192 + row*128 + ((ch ^ (row & 7))*16),
             kvsrc[q] + (size_t)(j*64 + row)*64 + ch*8);
      }
  };

  stageKV(0, 0); CPCOMMIT();
  __syncthreads();

  // Q fragments (persistent)
  uint32_t qf[4][4];
  {
    int r = warp*16 + (lane & 7) + ((lane >> 3) & 1) * 8;
#pragma unroll
    for (int kc = 0; kc < 4; kc++){
      int ch = kc*2 + (lane >> 4);
      uint32_t ad = smb + r*128 + ((ch ^ (r & 7)) * 16);
      LDSM4(qf[kc][0], qf[kc][1], qf[kc][2], qf[kc][3], ad);
    }
  }

  float o[8][4];
#pragma unroll
  for (int nt=0;nt<8;nt++)
#pragma unroll
    for (int e=0;e<4;e++) o[nt][e] = 0.f;
  float l0 = 0.f, l1 = 0.f;   // per-thread partial row sums

  const int r0g = qt*64 + warp*16 + g;
  const int r1g = r0g + 8;
  const int rBv = (lane & 7) + ((lane >> 4) << 3);
  const int chBv = (lane >> 3) & 1;
  const int rVv = (lane & 7) + (((lane >> 3) & 1) << 3);
  const int chVv = lane >> 4;

  for (int j = 0; j <= qt; j++){
    int s = j & 1;
    CPWAIT0();
    __syncthreads();
    if (j < qt){ stageKV(j + 1, s ^ 1); CPCOMMIT(); }

    const uint32_t kb = smb + FSM_KV + s*KV_STG;

    float sf[8][4];
#pragma unroll
    for (int nt=0;nt<8;nt++)
#pragma unroll
      for (int e=0;e<4;e++) sf[nt][e] = 0.f;

    // S = Q K^T (log2 domain; bounded by 11.54)
#pragma unroll
    for (int kc = 0; kc < 4; kc++){
#pragma unroll
      for (int ntp = 0; ntp < 4; ntp++){
        int r = ntp*16 + rBv;
        int ch = kc*2 + chBv;
        uint32_t ad = kb + r*128 + ((ch ^ (r & 7)) * 16);
        uint32_t b0,b1,b2,b3;
        LDSM4(b0,b1,b2,b3, ad);
        MMAH(sf[2*ntp],   qf[kc], b0, b1);
        MMAH(sf[2*ntp+1], qf[kc], b2, b3);
      }
    }

    // causal mask (diagonal tile only)
    if (j == qt){
#pragma unroll
      for (int nt = 0; nt < 8; nt++){
        int c0 = j*64 + nt*8 + 2*t;
        if (c0     > r0g) sf[nt][0] = -1e30f;
        if (c0 + 1 > r0g) sf[nt][1] = -1e30f;
        if (c0     > r1g) sf[nt][2] = -1e30f;
        if (c0 + 1 > r1g) sf[nt][3] = -1e30f;
      }
    }

    // P = 2^s in fp16x2 (no max, no bias) — output IS the packed A-fragment
    uint32_t pf[16];
#pragma unroll
    for (int nt = 0; nt < 8; nt++){
      __half2 e0 = h2exp2(__floats2half2_rn(sf[nt][0], sf[nt][1]));
      __half2 e1 = h2exp2(__floats2half2_rn(sf[nt][2], sf[nt][3]));
      pf[2*nt]   = *(uint32_t*)&e0;
      pf[2*nt+1] = *(uint32_t*)&e1;
      float2 f0 = __half22float2(e0), f1 = __half22float2(e1);
      l0 += f0.x + f0.y;  l1 += f1.x + f1.y;
    }

    // O += P V
    const uint32_t vb = kb + 8192;
#pragma unroll
    for (int kc = 0; kc < 4; kc++){
      uint32_t ph[4] = { pf[4*kc], pf[4*kc+1], pf[4*kc+2], pf[4*kc+3] };
#pragma unroll
      for (int ntp = 0; ntp < 4; ntp++){
        int r = kc*16 + rVv;
        int ch = ntp*2 + chVv;
        uint32_t ad = vb + r*128 + ((ch ^ (r & 7)) * 16);
        uint32_t w0,w1,w2,w3;
        LDSM4T(w0,w1,w2,w3, ad);
        MMAH(o[2*ntp],   ph, w0, w1);
        MMAH(o[2*ntp+1], ph, w2, w3);
      }
    }
  }

  // single row-sum reduction AFTER the loop
  l0 += __shfl_xor_sync(0xffffffffu, l0, 1);
  l0 += __shfl_xor_sync(0xffffffffu, l0, 2);
  l1 += __shfl_xor_sync(0xffffffffu, l1, 1);
  l1 += __shfl_xor_sync(0xffffffffu, l1, 2);

  float inv0 = 1.f / l0, inv1 = 1.f / l1;
  size_t ob0 = ((size_t)(b*Lc + qt*64 + warp*16 + g) * Hc + h) * HDc;
  size_t ob1 = ob0 + (size_t)8 * Hc * HDc;
#pragma unroll
  for (int nt = 0; nt < 8; nt++){
    int d = nt*8 + 2*t;
    __half2 a = { __float2half_rn(o[nt][0]*inv0), __float2half_rn(o[nt][1]*inv0) };
    __half2 c = { __float2half_rn(o[nt][2]*inv1), __float2half_rn(o[nt][3]*inv1) };
    *(__half2*)(O + ob0 + d) = a;
    *(__half2*)(O + ob1 + d) = c;
  }
}

// ---------------------------------------------------------------------------
extern "C" void kernel_launch(void* const* d_in, const int* in_sizes, int n_in,
                              void* d_out, int out_size)
{
  const float* x   = (const float*)d_in[0];
  const float* Wq  = (const float*)d_in[1];
  const float* Wk  = (const float*)d_in[2];
  const float* Wv  = (const float*)d_in[3];
  const float* Wo  = (const float*)d_in[4];
  const float* qnw = (const float*)d_in[5];
  const float* knw = (const float*)d_in[6];
  float* out = (float*)d_out;

  half_t *x16,*wqkv,*wo,*at,*qq,*kk,*vv;
  cudaGetSymbolAddress((void**)&x16, g_x16);
  cudaGetSymbolAddress((void**)&wqkv, g_wqkvT);
  cudaGetSymbolAddress((void**)&wo, g_woT);
  cudaGetSymbolAddress((void**)&qq, g_q);
  cudaGetSymbolAddress((void**)&kk, g_k);  cudaGetSymbolAddress((void**)&vv, g_v);
  cudaGetSymbolAddress((void**)&at, g_at);

  const int M = Mtok;

  // (1) activation convert
  xcvt<<<(M*Dc/4 + 255)/256, 256>>>(x, x16, M*Dc/4);
  // (2) all weight transposes in one launch
  wsplit_all<<<dim3(64, 64, 4), dim3(32,8)>>>(Wq, Wk, Wv, Wo, wqkv, wo);

  // (3) fused QKV projection + RMSNorm + RoPE -> head-major fp16
  cudaFuncSetAttribute(gemm_qkv, cudaFuncAttributeMaxDynamicSharedMemorySize, 2*GSTG1);
  gemm_qkv<<<dim3(QKVN/128, M/128), 256, 2*GSTG1>>>(x16, wqkv, qnw, knw, qq, kk, vv);

  // (4) flash attention (max-free softmax)
  cudaFuncSetAttribute(flash_tc, cudaFuncAttributeMaxDynamicSharedMemorySize, FLASH_SMEM);
  flash_tc<<<dim3(Lc/64, Hc, Bc), 128, FLASH_SMEM>>>(qq, kk, vv, at);

  // (5) output projection
  cudaFuncSetAttribute(gemm_fp16, cudaFuncAttributeMaxDynamicSharedMemorySize, 2*GSTG1);
  gemm_fp16<<<dim3(Dc/128, M/128), 256, 2*GSTG1>>>(at, wo, out, M, Dc, Dc);
}